// round 17
// baseline (speedup 1.0000x reference)
#include <cuda_runtime.h>
#include <stdint.h>

#define LQ 512
#define BQ 8
#define DQ 64
#define HQ 256
#define NROW 4096
#define GDIM 1024

typedef unsigned long long ull;

__device__ float g_attn [BQ*LQ*DQ];
__device__ float g_lines[3*NROW*DQ];
__device__ float g_xg   [3*NROW*GDIM];
__device__ float g_h0   [3*NROW*HQ];
__device__ float g_h1   [3*NROW*HQ];
__device__ float g_part [32*2*HQ];

static __device__ __forceinline__ float tanh_fast(float x) {
    float y; asm("tanh.approx.f32 %0, %1;" : "=f"(y) : "f"(x)); return y;
}
static __device__ __forceinline__ float sigmoid_t(float x) {
    return fmaf(0.5f, tanh_fast(0.5f*x), 0.5f);
}
static __device__ __forceinline__ ull pack2(float lo, float hi) {
    ull r; asm("mov.b64 %0, {%1, %2};" : "=l"(r) : "f"(lo), "f"(hi)); return r;
}
static __device__ __forceinline__ void ffma2(ull& acc, ull w, ull h) {
    asm("fma.rn.f32x2 %0, %1, %2, %0;" : "+l"(acc) : "l"(w), "l"(h));
}
static __device__ __forceinline__ ull addp2(ull a, ull b) {
    ull r; asm("add.rn.f32x2 %0, %1, %2;" : "=l"(r) : "l"(a), "l"(b)); return r;
}
static __device__ __forceinline__ float pairsum(ull v) {
    float lo, hi; asm("mov.b64 {%0, %1}, %2;" : "=f"(lo), "=f"(hi) : "l"(v));
    return lo + hi;
}
static __device__ __forceinline__ uint32_t smem_u32(const void* p) {
    uint32_t a;
    asm("{ .reg .u64 t; cvta.to.shared.u64 t, %1; cvt.u32.u64 %0, t; }" : "=r"(a) : "l"(p));
    return a;
}
static __device__ __forceinline__ float blockSum(float v, float* red, int nw) {
    #pragma unroll
    for (int o = 16; o; o >>= 1) v += __shfl_xor_sync(0xffffffffu, v, o);
    if ((threadIdx.x & 31) == 0) red[threadIdx.x >> 5] = v;
    __syncthreads();
    float r = red[0];
    for (int i = 1; i < nw; i++) r += red[i];
    __syncthreads();
    return r;
}
static __device__ __forceinline__ float blockMax(float v, float* red, int nw) {
    #pragma unroll
    for (int o = 16; o; o >>= 1) v = fmaxf(v, __shfl_xor_sync(0xffffffffu, v, o));
    if ((threadIdx.x & 31) == 0) red[threadIdx.x >> 5] = v;
    __syncthreads();
    float r = red[0];
    for (int i = 1; i < nw; i++) r = fmaxf(r, red[i]);
    __syncthreads();
    return r;
}

__global__ __launch_bounds__(128) void attn_kernel(const float* __restrict__ x,
                                                   const float* __restrict__ attn_w)
{
    __shared__ float xl[DQ];
    __shared__ float s1[LQ], s2[LQ], p1[LQ], p2[LQ];
    __shared__ float red[4];
    __shared__ float comb[3][DQ];
    const int l = blockIdx.x, b = blockIdx.y, tid = threadIdx.x;
    const float* xb = x + (size_t)b * LQ * DQ;

    if (tid < DQ) xl[tid] = xb[(size_t)l * DQ + tid];
    __syncthreads();

    for (int m = tid; m <= l; m += 128) {
        const float4* row = (const float4*)(xb + (size_t)m * DQ);
        float dot = 0.f, ts = 0.f;
        #pragma unroll
        for (int q = 0; q < 16; q++) {
            float4 v = row[q];
            float a0 = xl[4*q+0], a1 = xl[4*q+1], a2 = xl[4*q+2], a3 = xl[4*q+3];
            dot += a0*v.x + a1*v.y + a2*v.z + a3*v.w;
            ts  += tanh_fast(a0+v.x) + tanh_fast(a1+v.y)
                 + tanh_fast(a2+v.z) + tanh_fast(a3+v.w);
        }
        s1[m] = dot; s2[m] = ts;
    }
    __syncthreads();

    float m1 = -1e30f, m3 = -1e30f;
    for (int m = tid; m <= l; m += 128) { m1 = fmaxf(m1, s1[m]); m3 = fmaxf(m3, s2[m]); }
    m1 = blockMax(m1, red, 4);
    m3 = blockMax(m3, red, 4);
    float m2 = m1 * 0.125f;

    float z1 = 0.f, z2 = 0.f, z3 = 0.f;
    for (int m = tid; m <= l; m += 128) {
        float e1 = __expf(s1[m] - m1);
        float e2 = __expf(s1[m]*0.125f - m2);
        float e3 = __expf(s2[m] - m3);
        p1[m] = e1; p2[m] = e2; s2[m] = e3;
        z1 += e1; z2 += e2; z3 += e3;
    }
    z1 = blockSum(z1, red, 4);
    z2 = blockSum(z2, red, 4);
    z3 = blockSum(z3, red, 4);
    const float i1 = 1.f/z1, i2 = 1.f/z2, i3 = 1.f/z3;

    const int d = tid & 63, half = tid >> 6;
    float aP = 0.f, aS = 0.f, aA = 0.f;
    for (int m = half; m <= l; m += 2) {
        float xv = xb[(size_t)m * DQ + d];
        aP += p1[m]*xv; aS += p2[m]*xv; aA += s2[m]*xv;
    }
    if (half) { comb[0][d] = aP; comb[1][d] = aS; comb[2][d] = aA; }
    __syncthreads();
    if (!half) {
        aP = (aP + comb[0][d]) * i1;
        aS = (aS + comb[1][d]) * i2;
        aA = (aA + comb[2][d]) * i3;
        float w0 = attn_w[(size_t)(0*LQ + l)*DQ + d];
        float w1 = attn_w[(size_t)(1*LQ + l)*DQ + d];
        float w2 = attn_w[(size_t)(2*LQ + l)*DQ + d];
        float inv = 1.f/(w0 + w1 + w2);
        g_attn[((size_t)b*LQ + l)*DQ + d] = (aP*w0 + aA*w1 + aS*w2)*inv;
    }
}

__global__ __launch_bounds__(256) void bn1_kernel(const float* __restrict__ src,
                                                  const float* __restrict__ gamma,
                                                  const float* __restrict__ beta)
{
    __shared__ float vals[NROW];
    __shared__ float red[8];
    const int d = blockIdx.x, line = blockIdx.y, tid = threadIdx.x;
    float s = 0.f, ss = 0.f;
    for (int idx = tid; idx < NROW; idx += 256) {
        size_t off = (size_t)idx * DQ + d;
        float v;
        if (line == 0)      v = src[off];
        else if (line == 1) v = src[off] + g_attn[off];
        else                v = g_attn[off];
        vals[idx] = v; s += v; ss += v*v;
    }
    s  = blockSum(s,  red, 8);
    ss = blockSum(ss, red, 8);
    float mu  = s * (1.f/NROW);
    float var = ss * (1.f/NROW) - mu*mu;
    float scale = gamma[line*DQ + d] * rsqrtf(var + 1e-5f);
    float shift = beta [line*DQ + d] - mu*scale;
    float* dst = g_lines + (size_t)line * NROW * DQ;
    for (int idx = tid; idx < NROW; idx += 256) {
        int bb = idx >> 9, ll = idx & 511;
        dst[(size_t)(ll*8 + bb)*DQ + d] = vals[idx]*scale + shift;
    }
}

// ---- GEMM (64x64 tile, 256 threads) ----
__global__ __launch_bounds__(256) void gemm_kernel(const float* __restrict__ W,
                                                   const float* __restrict__ bias1,
                                                   const float* __restrict__ bias2,
                                                   int K, int phase)
{
    __shared__ float As[16][68];
    __shared__ float Bs[16][68];
    const int stack = blockIdx.z;
    const float* Ab = (phase ? g_h0 : g_lines) + (size_t)stack * NROW * K;
    const float* Wb = W + (size_t)stack * GDIM * K;
    const float* b1 = bias1 + stack * GDIM;
    const float* b2 = bias2 + stack * GDIM;
    float* Cb = g_xg + (size_t)stack * NROW * GDIM;
    const int m0 = blockIdx.x * 64, n0 = blockIdx.y * 64;
    const int tid = threadIdx.x;
    const int tm = tid & 15, tn = tid >> 4;
    const int li = tid >> 2, lj = tid & 3;
    float acc[4][4] = {};
    for (int k0 = 0; k0 < K; k0 += 16) {
        float4 av = *(const float4*)&Ab[(size_t)(m0+li)*K + k0 + lj*4];
        float4 wv = *(const float4*)&Wb[(size_t)(n0+li)*K + k0 + lj*4];
        As[lj*4+0][li] = av.x; As[lj*4+1][li] = av.y; As[lj*4+2][li] = av.z; As[lj*4+3][li] = av.w;
        Bs[lj*4+0][li] = wv.x; Bs[lj*4+1][li] = wv.y; Bs[lj*4+2][li] = wv.z; Bs[lj*4+3][li] = wv.w;
        __syncthreads();
        #pragma unroll
        for (int kk = 0; kk < 16; kk++) {
            float4 a  = *(const float4*)&As[kk][tm*4];
            float4 w4 = *(const float4*)&Bs[kk][tn*4];
            float ar[4] = {a.x, a.y, a.z, a.w};
            float wr[4] = {w4.x, w4.y, w4.z, w4.w};
            #pragma unroll
            for (int i2 = 0; i2 < 4; i2++)
                #pragma unroll
                for (int j2 = 0; j2 < 4; j2++)
                    acc[i2][j2] = fmaf(ar[i2], wr[j2], acc[i2][j2]);
        }
        __syncthreads();
    }
    #pragma unroll
    for (int j2 = 0; j2 < 4; j2++) {
        int n = n0 + tn*4 + j2;
        float bsum = b1[n] + b2[n];
        #pragma unroll
        for (int i2 = 0; i2 < 4; i2++) {
            int m = m0 + tm*4 + i2;
            Cb[(size_t)m*GDIM + n] = acc[i2][j2] + bsum;
        }
    }
}

// ---- LSTM: cluster of 8 CTAs; warp-local gates (no per-step __syncthreads) ----
// warp w owns units {2w, 2w+1} x 4 gates; lane owns 8 k.
// After butterfly, lane l holds value v=(l>>1)&15 with v = uo*8 + g*2 + b.
// Owner lanes {0,2,16,18} (g=0) gather g=1..3 from lanes +4,+8,+12.
#define HPAD 288
__global__ __launch_bounds__(512, 1) void lstm_kernel(const float* __restrict__ Whh,
                                                      int phase)
{
    const int ug = blockIdx.x, bg = blockIdx.y, stack = blockIdx.z;
    const int tid = threadIdx.x;
    const int w = tid >> 5, lane = tid & 31;
    const int j0 = ug * 32;

    __shared__ __align__(16) float hsx[2][2][HPAD];

    // wp[idx][q], idx = uo*4 + g : row rglob = g*256 + j0 + (2w+uo)
    ull wp[8][4];
    #pragma unroll
    for (int idx = 0; idx < 8; idx++) {
        int uo = idx >> 2, g = idx & 3;
        int rglob = (g << 8) + j0 + (w*2 + uo);
        const float* wrow = Whh + ((size_t)stack << 18) + ((size_t)rglob << 8) + lane*8;
        #pragma unroll
        for (int q = 0; q < 4; q++) wp[idx][q] = pack2(wrow[2*q], wrow[2*q+1]);
    }
    for (int i = tid; i < 2*2*HPAD; i += 512) ((float*)hsx)[i] = 0.f;

    const float* xg_s = g_xg + (size_t)stack * NROW * GDIM;
    float* hseq_s = (phase ? g_h1 : g_h0) + (size_t)stack * NROW * HQ;

    const bool is_owner = (lane == 0) || (lane == 2) || (lane == 16) || (lane == 18);
    const int uo_o = (lane >> 4) & 1;
    const int b_o  = (lane >> 1) & 1;
    const int u_own = w*2 + uo_o;            // local unit 0..31
    const int k_own = j0 + u_own;            // global k
    const int bglob = bg*2 + b_o;
    float c_state = 0.f;

    float xr0 = 0.f, xr1 = 0.f, xr2 = 0.f, xr3 = 0.f;
    if (is_owner) {
        const float* xp = xg_s + (size_t)(0*8 + bglob)*GDIM + k_own;
        xr0 = xp[0]; xr1 = xp[256]; xr2 = xp[512]; xr3 = xp[768];
    }
    __syncthreads();
    asm volatile("barrier.cluster.arrive.aligned;" ::: "memory");
    asm volatile("barrier.cluster.wait.aligned;" ::: "memory");

    const int hbase = lane*8 + (lane >> 2)*4;   // padded float index of k=lane*8

    for (int t = 0; t < LQ; t++) {
        const int par = t & 1;
        float a[16];   // a[idx*2 + b], idx = uo*4+g  ->  v = uo*8+g*2+b
        #pragma unroll
        for (int b = 0; b < 2; b++) {
            ulonglong2 hA = *(const ulonglong2*)&hsx[par][b][hbase];
            ulonglong2 hB = *(const ulonglong2*)&hsx[par][b][hbase + 4];
            ull hq0 = hA.x, hq1 = hA.y, hq2 = hB.x, hq3 = hB.y;
            #pragma unroll
            for (int idx = 0; idx < 8; idx++) {
                ull e = pack2(0.f, 0.f), f = pack2(0.f, 0.f);
                ffma2(e, wp[idx][0], hq0);
                ffma2(f, wp[idx][1], hq1);
                ffma2(e, wp[idx][2], hq2);
                ffma2(f, wp[idx][3], hq3);
                a[idx*2 + b] = pairsum(addp2(e, f));
            }
        }
        // pairwise-merge butterfly: 16 values -> lane l holds v=(l>>1)&15
        #pragma unroll
        for (int bit = 16, vals = 16; bit >= 2; bit >>= 1, vals >>= 1) {
            const int half = vals >> 1;
            const bool up = (lane & bit) != 0;
            #pragma unroll
            for (int i = 0; i < 8; i++) {
                if (i < half) {
                    float send = up ? a[i] : a[i + half];
                    float keep = up ? a[i + half] : a[i];
                    float recv = __shfl_xor_sync(0xffffffffu, send, bit);
                    a[i] = keep + recv;
                }
            }
        }
        a[0] += __shfl_xor_sync(0xffffffffu, a[0], 1);

        // gather the 4 gates to owner lanes (g-th value at lane+4g)
        float gv1 = __shfl_sync(0xffffffffu, a[0], (lane + 4) & 31);
        float gv2 = __shfl_sync(0xffffffffu, a[0], (lane + 8) & 31);
        float gv3 = __shfl_sync(0xffffffffu, a[0], (lane + 12) & 31);

        float hreg = 0.f;
        if (is_owner) {
            float pi = a[0] + xr0;
            float pf = gv1  + xr1;
            float pg = gv2  + xr2;
            float po = gv3  + xr3;
            float ig = sigmoid_t(pi);
            float fg = sigmoid_t(pf);
            float gg = tanh_fast(pg);
            float og = sigmoid_t(po);
            float c  = fg * c_state + ig * gg;
            c_state = c;
            hreg = og * tanh_fast(c);
        }
        // pair uo=0 with uo=1 (lanes l and l^16, same b)
        float hnb = __shfl_xor_sync(0xffffffffu, hreg, 16);
        if (lane == 0 || lane == 2) {          // uo=0 owners store the b64 pair
            const int k = j0 + w*2;            // even
            const int fidx = k + (k >> 5)*4;   // padded index; pair adjacent
            ull hv2 = pack2(hreg, hnb);        // {h_{2w}, h_{2w+1}}
            uint32_t laddr = smem_u32(&hsx[par^1][b_o][fidx]);
            #pragma unroll
            for (int tgt = 0; tgt < 8; tgt++) {
                uint32_t raddr;
                asm volatile("mapa.shared::cluster.u32 %0, %1, %2;"
                             : "=r"(raddr) : "r"(laddr), "r"(tgt));
                asm volatile("st.shared::cluster.b64 [%0], %1;"
                             :: "r"(raddr), "l"(hv2) : "memory");
            }
        }
        // arrive (release) — per-thread ordered after its hs[par] reads & stores
        asm volatile("barrier.cluster.arrive.aligned;" ::: "memory");
        // overlap gmem traffic with barrier latency
        if (is_owner) {
            hseq_s[(size_t)(t*8 + bglob)*HQ + k_own] = hreg;
            if (t + 1 < LQ) {
                const float* xp = xg_s + (size_t)((t+1)*8 + bglob)*GDIM + k_own;
                xr0 = xp[0]; xr1 = xp[256]; xr2 = xp[512]; xr3 = xp[768];
            }
        }
        asm volatile("barrier.cluster.wait.aligned;" ::: "memory");
    }
}

__global__ __launch_bounds__(256) void bn2stats_kernel(const float* __restrict__ cat_w)
{
    const int h = threadIdx.x, blk = blockIdx.x;
    float s = 0.f, ss = 0.f;
    for (int tt = 0; tt < 16; tt++) {
        int t = blk*16 + tt;
        float w0 = cat_w[(size_t)(0*LQ + t)*HQ + h];
        float w1 = cat_w[(size_t)(1*LQ + t)*HQ + h];
        float w2 = cat_w[(size_t)(2*LQ + t)*HQ + h];
        float inv = 1.f/(w0 + w1 + w2);
        w0 *= inv; w1 *= inv; w2 *= inv;
        #pragma unroll
        for (int b = 0; b < 8; b++) {
            size_t row = (size_t)(t*8 + b)*HQ + h;
            float v = g_h1[row]*w0 + g_h1[row + (size_t)NROW*HQ]*w1
                    + g_h1[row + 2*(size_t)NROW*HQ]*w2;
            s += v; ss += v*v;
        }
    }
    g_part[(blk*2 + 0)*HQ + h] = s;
    g_part[(blk*2 + 1)*HQ + h] = ss;
}

__global__ __launch_bounds__(256) void final_kernel(const float* __restrict__ cat_w,
                                                    const float* __restrict__ g2,
                                                    const float* __restrict__ b2,
                                                    const float* __restrict__ fcW,
                                                    const float* __restrict__ fcb,
                                                    float* __restrict__ out)
{
    __shared__ float catn[HQ][BQ];
    const int tid = threadIdx.x;
    float s = 0.f, ss = 0.f;
    for (int blk = 0; blk < 32; blk++) {
        s  += g_part[(blk*2 + 0)*HQ + tid];
        ss += g_part[(blk*2 + 1)*HQ + tid];
    }
    float mu  = s * (1.f/NROW);
    float var = ss * (1.f/NROW) - mu*mu;
    float scale = g2[tid] * rsqrtf(var + 1e-5f);
    float shift = b2[tid] - mu*scale;

    const int t = LQ - 1;
    float w0 = cat_w[(size_t)(0*LQ + t)*HQ + tid];
    float w1 = cat_w[(size_t)(1*LQ + t)*HQ + tid];
    float w2 = cat_w[(size_t)(2*LQ + t)*HQ + tid];
    float inv = 1.f/(w0 + w1 + w2);
    w0 *= inv; w1 *= inv; w2 *= inv;
    #pragma unroll
    for (int b = 0; b < 8; b++) {
        size_t row = (size_t)(t*8 + b)*HQ + tid;
        float v = g_h1[row]*w0 + g_h1[row + (size_t)NROW*HQ]*w1
                + g_h1[row + 2*(size_t)NROW*HQ]*w2;
        catn[tid][b] = v*scale + shift;
    }
    __syncthreads();
    if (tid < 64) {
        int b = tid >> 3, c = tid & 7;
        float acc = fcb[c];
        for (int hh = 0; hh < HQ; hh++) acc = fmaf(catn[hh][b], fcW[c*HQ + hh], acc);
        out[b*8 + c] = acc;
    }
}

static void launch_lstm(const float* Whh, int phase, cudaStream_t st = 0)
{
    cudaLaunchConfig_t cfg = {};
    cfg.gridDim  = dim3(8, 4, 3);
    cfg.blockDim = dim3(512, 1, 1);
    cfg.dynamicSmemBytes = 0;
    cfg.stream = st;
    cudaLaunchAttribute attrs[1];
    attrs[0].id = cudaLaunchAttributeClusterDimension;
    attrs[0].val.clusterDim = {8, 1, 1};
    cfg.attrs = attrs;
    cfg.numAttrs = 1;
    cudaLaunchKernelEx(&cfg, lstm_kernel, Whh, phase);
}

extern "C" void kernel_launch(void* const* d_in, const int* in_sizes, int n_in,
                              void* d_out, int out_size)
{
    const float* src    = (const float*)d_in[0];
    const float* attn_w = (const float*)d_in[1];
    const float* cat_w  = (const float*)d_in[2];
    const float* bn1_g  = (const float*)d_in[3];
    const float* bn1_b  = (const float*)d_in[4];
    const float* bn2_g  = (const float*)d_in[5];
    const float* bn2_b  = (const float*)d_in[6];
    const float* Wih0   = (const float*)d_in[7];
    const float* Whh0   = (const float*)d_in[8];
    const float* bih0   = (const float*)d_in[9];
    const float* bhh0   = (const float*)d_in[10];
    const float* Wih1   = (const float*)d_in[11];
    const float* Whh1   = (const float*)d_in[12];
    const float* bih1   = (const float*)d_in[13];
    const float* bhh1   = (const float*)d_in[14];
    const float* fcW    = (const float*)d_in[15];
    const float* fcb    = (const float*)d_in[16];
    float* out = (float*)d_out;

    attn_kernel<<<dim3(LQ, BQ), 128>>>(src, attn_w);                  // 0
    bn1_kernel<<<dim3(DQ, 3), 256>>>(src, bn1_g, bn1_b);              // 1
    gemm_kernel<<<dim3(64, 16, 3), 256>>>(Wih0, bih0, bhh0, 64, 0);   // 2
    launch_lstm(Whh0, 0);                                             // 3
    gemm_kernel<<<dim3(64, 16, 3), 256>>>(Wih1, bih1, bhh1, 256, 1);  // 4
    launch_lstm(Whh1, 1);                                             // 5  <- ncu capture slot
    bn2stats_kernel<<<32, 256>>>(cat_w);                              // 6
    final_kernel<<<1, 256>>>(cat_w, bn2_g, bn2_b, fcW, fcb, out);     // 7
}